// round 15
// baseline (speedup 1.0000x reference)
#include <cuda_runtime.h>
#include <cuda_bf16.h>
#include <cuda_fp16.h>
#include <cstdint>

// Problem constants
#define LQ      43054
#define NHEADS  8

// Padded value geometry: each level padded +2 on every side.
#define PADROWS 45822
#define ZPN     (PADROWS * 8)     // one zero-task per (pixel, head)
#define ZPB     ((ZPN + 255) / 256)   // zero-pad blocks needed: 1432

// Scratch (device globals; no runtime allocation allowed)
// Head-major padded value: [head][padded pixel][32 fp16] (64B per pixel-head)
__device__ __half g_value_h[NHEADS * PADROWS * 32];
__device__ float  g_qout[LQ * 384];             // [0,256)=offsets, [256,384)=logits
__device__ __half g_acc[LQ * 256];              // msda out (fp16)
__device__ __half g_Wv[256 * 256];
__device__ __half g_Wq[384 * 256];              // merged Ws|Wa
__device__ __half g_Wo[256 * 256];
__device__ float g_bq[384];                     // merged bias bs|ba

#define SW128(o) ((o) ^ (((o) >> 3) & 0x70))

__device__ __forceinline__ uint32_t smem_u32(const void* p) {
    uint32_t a;
    asm("{ .reg .u64 t; cvta.to.shared.u64 t, %1; cvt.u32.u64 %0, t; }" : "=r"(a) : "l"(p));
    return a;
}
__device__ __forceinline__ void ldsm4(uint32_t r[4], uint32_t addr) {
    asm volatile("ldmatrix.sync.aligned.m8n8.x4.shared.b16 {%0,%1,%2,%3}, [%4];"
        : "=r"(r[0]), "=r"(r[1]), "=r"(r[2]), "=r"(r[3]) : "r"(addr));
}
__device__ __forceinline__ void mma_f16(float d[4], const uint32_t a[4],
                                        uint32_t b0, uint32_t b1) {
    asm volatile("mma.sync.aligned.m16n8k16.row.col.f32.f16.f16.f32 "
        "{%0,%1,%2,%3}, {%4,%5,%6,%7}, {%8,%9}, {%0,%1,%2,%3};"
        : "+f"(d[0]), "+f"(d[1]), "+f"(d[2]), "+f"(d[3])
        : "r"(a[0]), "r"(a[1]), "r"(a[2]), "r"(a[3]), "r"(b0), "r"(b1));
}
__device__ __forceinline__ uint32_t packh2(float x, float y) {
    __half2 h = __floats2half2_rn(x, y);
    return *(uint32_t*)&h;
}
__device__ __forceinline__ void cpa16(uint32_t d, const void* s) {
    asm volatile("cp.async.cg.shared.global [%0], [%1], 16;" :: "r"(d), "l"(s));
}
#define CP_COMMIT() asm volatile("cp.async.commit_group;" ::: "memory")
template <int Ngrp>
__device__ __forceinline__ void cp_wait() {
    asm volatile("cp.async.wait_group %0;" :: "n"(Ngrp) : "memory");
}

// Map original value row -> padded row index (compile-time divisors).
__device__ __forceinline__ int pad_row(int r) {
    if (r < 32400) { int cy = r / 180, cx = r - cy * 180; return (cy + 2) * 184 + cx + 2; }
    if (r < 40500) { int rr = r - 32400; int cy = rr / 90, cx = rr - cy * 90; return 33856 + (cy + 2) * 94 + cx + 2; }
    if (r < 42525) { int rr = r - 40500; int cy = rr / 45, cx = rr - cy * 45; return 42692 + (cy + 2) * 49 + cx + 2; }
    { int rr = r - 42525; int cy = rr / 23, cx = rr - cy * 23; return 45093 + (cy + 2) * 27 + cx + 2; }
}

// ---------------------------------------------------------------------------
// Weight prep only: fp16 transpose + merged bias (zero-pad moved into proj).
// ---------------------------------------------------------------------------
__global__ __launch_bounds__(256) void prep_weights(
    const float* __restrict__ Wv, const float* __restrict__ Ws,
    const float* __restrict__ Wa, const float* __restrict__ Wo,
    const float* __restrict__ bs, const float* __restrict__ ba,
    __half* __restrict__ wv, __half* __restrict__ wq, __half* __restrict__ wo,
    float* __restrict__ bq)
{
    int idx = blockIdx.x * 256 + threadIdx.x;
    const float* W;
    __half* dst;
    int N, base, nofs;
    if (idx < 65536)        { W = Wv; dst = wv; N = 256; base = 0;      nofs = 0; }
    else if (idx < 131072)  { W = Ws; dst = wq; N = 256; base = 65536;  nofs = 0; }
    else if (idx < 163840)  { W = Wa; dst = wq; N = 128; base = 131072; nofs = 256; }
    else if (idx < 229376)  { W = Wo; dst = wo; N = 256; base = 163840; nofs = 0; }
    else if (idx < 229376 + 256) { bq[idx - 229376] = bs[idx - 229376]; return; }
    else if (idx < 229376 + 384) { bq[idx - 229376] = ba[idx - 229632]; return; }
    else return;
    int j = idx - base;
    int k = j / N, n = j % N + nofs;
    dst[n * 256 + k] = __float2half_rn(W[j]);
}

// ---------------------------------------------------------------------------
// Fused projection kernel + value border zeroing:
//   bx<2  : value path -> head-major padded fp16 value (interior pixels)
//   2<=bx<5: q path    -> fp32 [Lq,384] offsets|logits
//   bx>=5 : zero-pad border pixels of the value buffer (disjoint writes)
// ---------------------------------------------------------------------------
__global__ __launch_bounds__(256, 2) void proj_fused(
    const float* __restrict__ Av, const float* __restrict__ Aq,
    const __half* __restrict__ Bv, const __half* __restrict__ Bq,
    const float* __restrict__ biasv, const float* __restrict__ biasq,
    __half* __restrict__ Cv, float* __restrict__ Cq, int M, int GBY)
{
    // ---- zero-pad path
    if (blockIdx.x >= 5) {
        int bid = (blockIdx.x - 5) * GBY + blockIdx.y;
        int idx = bid * 256 + threadIdx.x;
        if (idx >= ZPN) return;
        int row = idx >> 3, h = idx & 7;
        bool pad;
        if (row < 33856)      { int py = row / 184, px = row - py * 184;
                                pad = (py < 2) | (py >= 182) | (px < 2) | (px >= 182); }
        else if (row < 42692) { int r2 = row - 33856; int py = r2 / 94, px = r2 - py * 94;
                                pad = (py < 2) | (py >= 92) | (px < 2) | (px >= 92); }
        else if (row < 45093) { int r2 = row - 42692; int py = r2 / 49, px = r2 - py * 49;
                                pad = (py < 2) | (py >= 47) | (px < 2) | (px >= 47); }
        else                  { int r2 = row - 45093; int py = r2 / 27, px = r2 - py * 27;
                                pad = (py < 2) | (py >= 25) | (px < 2) | (px >= 25); }
        if (pad) {
            uint4* d = (uint4*)((char*)Cv + ((size_t)h * PADROWS + row) * 64);
            d[0] = make_uint4(0, 0, 0, 0);
            d[1] = make_uint4(0, 0, 0, 0);
            d[2] = make_uint4(0, 0, 0, 0);
            d[3] = make_uint4(0, 0, 0, 0);
        }
        return;
    }

    extern __shared__ char smem[];
    const uint32_t sb = smem_u32(smem);
    constexpr int BOFF = 16384;

    const bool vpath = blockIdx.x < 2;
    const int bn = (vpath ? blockIdx.x : blockIdx.x - 2) * 128;
    const float* __restrict__ A = vpath ? Av : Aq;
    const __half* __restrict__ B = vpath ? Bv : Bq;
    const float* __restrict__ bias = vpath ? biasv : biasq;

    const int tid = threadIdx.x;
    const int wid = tid >> 5, lane = tid & 31;
    const int wm = (wid & 3) * 32;
    const int wn = (wid >> 2) * 64;
    const int bm = blockIdx.y * 128;

    float acc[2][8][4];
#pragma unroll
    for (int i = 0; i < 2; i++)
#pragma unroll
        for (int j = 0; j < 8; j++)
#pragma unroll
            for (int k = 0; k < 4; k++) acc[i][j][k] = 0.f;

    const int a_row = lane & 15;
    const int a_k8  = (lane >> 4) << 3;
    const int b_row = (lane & 7) + ((lane & 16) >> 1);
    const int b_k8  = lane & 8;

    const int ld_row = tid >> 1;
    const int ld_kh  = (tid & 1) * 32;
    const int grow   = bm + ld_row;
    const bool okA   = grow < M;

    auto issueB = [&](int c) {
        const int k0 = c * 64;
        const int n = bn + ld_row;
        const __half* s = &B[(size_t)n * 256 + k0 + ld_kh];
        const uint32_t bas = sb + BOFF + c * 16384;
#pragma unroll
        for (int jj = 0; jj < 4; jj++) {
            uint32_t off = SW128((uint32_t)(ld_row * 128 + (ld_kh + jj * 8) * 2));
            cpa16(bas + off, s + jj * 8);
        }
    };

    float4 vA[8];
    auto stageA = [&](int c) {
        const int k0 = c * 64;
        const float4* src = (const float4*)&A[(size_t)(okA ? grow : 0) * 256 + k0 + ld_kh];
#pragma unroll
        for (int j = 0; j < 8; j++)
            vA[j] = okA ? src[j] : make_float4(0.f, 0.f, 0.f, 0.f);
    };
    auto commitA = [&]() {
#pragma unroll
        for (int jj = 0; jj < 4; jj++) {
            float4 v0 = vA[jj * 2 + 0];
            float4 v1 = vA[jj * 2 + 1];
            uint4 hi4;
            uint32_t* hp = (uint32_t*)&hi4;
            hp[0] = packh2(v0.x, v0.y);
            hp[1] = packh2(v0.z, v0.w);
            hp[2] = packh2(v1.x, v1.y);
            hp[3] = packh2(v1.z, v1.w);
            uint32_t off = SW128((uint32_t)(ld_row * 128 + (ld_kh + jj * 8) * 2));
            *(uint4*)(smem + off) = hi4;
        }
    };

    // B-fragment double-buffered MMA chunk
    auto mma_chunk = [&](uint32_t bB) {
#pragma unroll
        for (int ks = 0; ks < 4; ks++) {
            uint32_t ah[2][4];
#pragma unroll
            for (int mt = 0; mt < 2; mt++) {
                uint32_t aoff = SW128((uint32_t)((wm + mt * 16 + a_row) * 128 +
                                                 (ks * 16 + a_k8) * 2));
                ldsm4(ah[mt], sb + aoff);
            }
            uint32_t b4[2][4];
            {
                uint32_t boff = SW128((uint32_t)((wn + b_row) * 128 +
                                                 (ks * 16 + b_k8) * 2));
                ldsm4(b4[0], bB + boff);
            }
#pragma unroll
            for (int ng = 0; ng < 4; ng++) {
                if (ng < 3) {
                    uint32_t boff = SW128((uint32_t)((wn + (ng + 1) * 16 + b_row) * 128 +
                                                     (ks * 16 + b_k8) * 2));
                    ldsm4(b4[(ng + 1) & 1], bB + boff);
                }
                const uint32_t* bb = b4[ng & 1];
                mma_f16(acc[0][ng * 2 + 0], ah[0], bb[0], bb[1]);
                mma_f16(acc[1][ng * 2 + 0], ah[1], bb[0], bb[1]);
                mma_f16(acc[0][ng * 2 + 1], ah[0], bb[2], bb[3]);
                mma_f16(acc[1][ng * 2 + 1], ah[1], bb[2], bb[3]);
            }
        }
    };

    issueB(0); CP_COMMIT();
    issueB(1); CP_COMMIT();
    issueB(2); CP_COMMIT();
    issueB(3); CP_COMMIT();
    stageA(0);
#pragma unroll
    for (int c = 0; c < 4; c++) {
        if (c > 0) __syncthreads();
        commitA();
        if (c < 3) stageA(c + 1);
        if (c == 0) cp_wait<3>();
        else if (c == 1) cp_wait<2>();
        else if (c == 2) cp_wait<1>();
        else cp_wait<0>();
        __syncthreads();
        mma_chunk(sb + BOFF + c * 16384);
    }

    // epilogue
    const int g = lane >> 2;
    const int cb = wn + (lane & 3) * 2;
    if (vpath) {
        int prow[2][2];
#pragma unroll
        for (int mt = 0; mt < 2; mt++) {
            int r0 = bm + wm + mt * 16 + g;
            prow[mt][0] = (r0 < M) ? pad_row(r0) : 0;
            prow[mt][1] = (r0 + 8 < M) ? pad_row(r0 + 8) : 0;
        }
#pragma unroll
        for (int nt = 0; nt < 8; nt++) {
            const int col = bn + cb + nt * 8;
            const int hh = col >> 5, ch = col & 31;
            const float b0 = bias[col], b1 = bias[col + 1];
#pragma unroll
            for (int mt = 0; mt < 2; mt++) {
                int r0 = bm + wm + mt * 16 + g;
                if (r0 < M)
                    *(__half2*)&Cv[((size_t)hh * PADROWS + prow[mt][0]) * 32 + ch] =
                        __floats2half2_rn(acc[mt][nt][0] + b0, acc[mt][nt][1] + b1);
                if (r0 + 8 < M)
                    *(__half2*)&Cv[((size_t)hh * PADROWS + prow[mt][1]) * 32 + ch] =
                        __floats2half2_rn(acc[mt][nt][2] + b0, acc[mt][nt][3] + b1);
            }
        }
    } else {
#pragma unroll
        for (int nt = 0; nt < 8; nt++) {
            const int col = bn + cb + nt * 8;
            const float b0 = bias[col], b1 = bias[col + 1];
#pragma unroll
            for (int mt = 0; mt < 2; mt++) {
                int r0 = bm + wm + mt * 16 + g;
                if (r0 < M)
                    *(float2*)&Cq[(size_t)r0 * 384 + col] =
                        make_float2(acc[mt][nt][0] + b0, acc[mt][nt][1] + b1);
                if (r0 + 8 < M)
                    *(float2*)&Cq[(size_t)(r0 + 8) * 384 + col] =
                        make_float2(acc[mt][nt][2] + b0, acc[mt][nt][3] + b1);
            }
        }
    }
}

// ---------------------------------------------------------------------------
// Output GEMM: out (fp32, N=256) = acc (fp16) @ Wo + bo
// ---------------------------------------------------------------------------
__global__ __launch_bounds__(256, 2) void gemm_out(
    const __half* __restrict__ AhG,
    const __half* __restrict__ B,
    const float* __restrict__ bias,
    float* __restrict__ C, int M)
{
    extern __shared__ char smem[];
    const uint32_t sb = smem_u32(smem);
    constexpr int BOFF = 16384;

    const int tid = threadIdx.x;
    const int wid = tid >> 5, lane = tid & 31;
    const int wm = (wid & 3) * 32;
    const int wn = (wid >> 2) * 64;
    const int bm = blockIdx.y * 128;
    const int bn = blockIdx.x * 128;

    float acc[2][8][4];
#pragma unroll
    for (int i = 0; i < 2; i++)
#pragma unroll
        for (int j = 0; j < 8; j++)
#pragma unroll
            for (int k = 0; k < 4; k++) acc[i][j][k] = 0.f;

    const int a_row = lane & 15;
    const int a_k8  = (lane >> 4) << 3;
    const int b_row = (lane & 7) + ((lane & 16) >> 1);
    const int b_k8  = lane & 8;

    const int ld_row = tid >> 1;
    const int ld_kh  = (tid & 1) * 32;
    const int grow   = bm + ld_row;
    const bool okA   = grow < M;

    auto issueB = [&](int c) {
        const int k0 = c * 64;
        const int n = bn + ld_row;
        const __half* s = &B[(size_t)n * 256 + k0 + ld_kh];
        const uint32_t bas = sb + BOFF + c * 16384;
#pragma unroll
        for (int jj = 0; jj < 4; jj++) {
            uint32_t off = SW128((uint32_t)(ld_row * 128 + (ld_kh + jj * 8) * 2));
            cpa16(bas + off, s + jj * 8);
        }
    };

    uint4 sA[4];
    auto stageA = [&](int c) {
        const int k0 = c * 64;
        const uint4* sh = (const uint4*)&AhG[(size_t)(okA ? grow : 0) * 256 + k0 + ld_kh];
#pragma unroll
        for (int j = 0; j < 4; j++)
            sA[j] = okA ? sh[j] : make_uint4(0, 0, 0, 0);
    };
    auto commitA = [&]() {
#pragma unroll
        for (int jj = 0; jj < 4; jj++) {
            uint32_t off = SW128((uint32_t)(ld_row * 128 + (ld_kh + jj * 8) * 2));
            *(uint4*)(smem + off) = sA[jj];
        }
    };

    auto mma_chunk = [&](uint32_t bB) {
#pragma unroll
        for (int ks = 0; ks < 4; ks++) {
            uint32_t ah[2][4];
#pragma unroll
            for (int mt = 0; mt < 2; mt++) {
                uint32_t aoff = SW128((uint32_t)((wm + mt * 16 + a_row) * 128 +
                                                 (ks * 16 + a_k8) * 2));
                ldsm4(ah[mt], sb + aoff);
            }
            uint32_t b4[2][4];
            {
                uint32_t boff = SW128((uint32_t)((wn + b_row) * 128 +
                                                 (ks * 16 + b_k8) * 2));
                ldsm4(b4[0], bB + boff);
            }
#pragma unroll
            for (int ng = 0; ng < 4; ng++) {
                if (ng < 3) {
                    uint32_t boff = SW128((uint32_t)((wn + (ng + 1) * 16 + b_row) * 128 +
                                                     (ks * 16 + b_k8) * 2));
                    ldsm4(b4[(ng + 1) & 1], bB + boff);
                }
                const uint32_t* bb = b4[ng & 1];
                mma_f16(acc[0][ng * 2 + 0], ah[0], bb[0], bb[1]);
                mma_f16(acc[1][ng * 2 + 0], ah[1], bb[0], bb[1]);
                mma_f16(acc[0][ng * 2 + 1], ah[0], bb[2], bb[3]);
                mma_f16(acc[1][ng * 2 + 1], ah[1], bb[2], bb[3]);
            }
        }
    };

    issueB(0); CP_COMMIT();
    issueB(1); CP_COMMIT();
    issueB(2); CP_COMMIT();
    issueB(3); CP_COMMIT();
    stageA(0);
#pragma unroll
    for (int c = 0; c < 4; c++) {
        if (c > 0) __syncthreads();
        commitA();
        if (c < 3) stageA(c + 1);
        if (c == 0) cp_wait<3>();
        else if (c == 1) cp_wait<2>();
        else if (c == 2) cp_wait<1>();
        else cp_wait<0>();
        __syncthreads();
        mma_chunk(sb + BOFF + c * 16384);
    }

    const int g = lane >> 2;
    const int cbase = bn + wn + (lane & 3) * 2;
#pragma unroll
    for (int nt = 0; nt < 8; nt++) {
        const int col = cbase + nt * 8;
        const float b0 = bias[col], b1 = bias[col + 1];
#pragma unroll
        for (int mt = 0; mt < 2; mt++) {
            int r0 = bm + wm + mt * 16 + g;
            if (r0 < M)
                *(float2*)&C[(size_t)r0 * 256 + col] =
                    make_float2(acc[mt][nt][0] + b0, acc[mt][nt][1] + b1);
            if (r0 + 8 < M)
                *(float2*)&C[(size_t)(r0 + 8) * 256 + col] =
                    make_float2(acc[mt][nt][2] + b0, acc[mt][nt][3] + b1);
        }
    }
}

// ---------------------------------------------------------------------------
// Sampling kernel: head-major value, 4 queries/block (512 thr), 2 heads/warp.
// ---------------------------------------------------------------------------
__global__ __launch_bounds__(512) void msda_sample(
    const __half* __restrict__ value,    // [8][PADROWS][32] fp16
    const float* __restrict__ qout,      // [Lq,384] offsets|logits
    const float* __restrict__ rp,        // [Lq,4,2]
    __half* __restrict__ accb)
{
    constexpr int WW[4] = {180, 90, 45, 23};
    constexpr int PB[4] = {0, 33856, 42692, 45093};

    __shared__ uint2 swo[4][NHEADS][16][4];   // [q-sub][head][point][corner]

    const int tid = threadIdx.x;
    const int qi = tid >> 7;
    const int q = blockIdx.x * 4 + qi;
    const int t7 = tid & 127;
    const int wid = t7 >> 5;
    const int lane = tid & 31;
    const int h2 = lane >> 4;
    const int h  = wid * 2 + h2;
    const int pt = lane & 15;
    const int cr = (lane >> 2) & 3;
    const int e  = lane & 3;

    // softmax over this head's 16 logits
    const float lg = qout[q * 384 + 256 + h * 16 + pt];
    float m = lg;
#pragma unroll
    for (int s = 8; s > 0; s >>= 1)
        m = fmaxf(m, __shfl_xor_sync(0xffffffffu, m, s));
    const float eo = __expf(lg - m);
    float ssum = eo;
#pragma unroll
    for (int s = 8; s > 0; s >>= 1)
        ssum += __shfl_xor_sync(0xffffffffu, ssum, s);
    const float aw = eo / ssum;

    // geometry: all 32 lanes (2 heads x 16 points)
    {
        const int l = pt >> 2;
        const int p = pt & 3;
        const int W = WW[l];
        const float2 rxy = *(const float2*)&rp[(q * 4 + l) * 2];
        const int oj = q * 384 + (((h * 4 + l) * 4) + p) * 2;
        const float2 oxy = *(const float2*)&qout[oj];
        const float x = fmaf(rxy.x, (float)W, oxy.x) - 0.5f;
        const float y = fmaf(rxy.y, (float)W, oxy.y) - 0.5f;
        const float xf = floorf(x), yf = floorf(y);
        const float dx = x - xf, dy = y - yf;
        const int xc = min(max((int)xf, -2), W);
        const int yc = min(max((int)yf, -2), W);
        const int B0 = (PB[l] + (yc + 2) * (W + 4) + (xc + 2)) * 64;   // 64B/pixel
        const float wx1 = aw * dx;
        const float wx0 = aw - wx1;
#pragma unroll
        for (int c = 0; c < 4; c++) {
            const int cxx = c & 1, cyy = c >> 1;
            const int off = B0 + (cyy * (W + 4) + cxx) * 64;
            const float w = (cxx ? wx1 : wx0) * (cyy ? dy : (1.f - dy));
            swo[qi][h][pt][c] = make_uint2(__float_as_uint(w), (uint32_t)off);
        }
    }
    __syncwarp();

    // gather: one LDG.128 per point per lane (16B of a corner pixel)
    const char* __restrict__ vb = (const char*)value + (size_t)h * PADROWS * 64 + e * 16;
    const uint2* __restrict__ sp = &swo[qi][h][0][cr];
    float acc[8];
#pragma unroll
    for (int j = 0; j < 8; j++) acc[j] = 0.f;

#pragma unroll
    for (int i = 0; i < 16; i++) {
        const uint2 wo = sp[i * 4];
        const float w = __uint_as_float(wo.x);
        const uint4 raw = *(const uint4*)(vb + wo.y);
        const __half2* hp = (const __half2*)&raw;
#pragma unroll
        for (int j = 0; j < 4; j++) {
            const float2 f = __half22float2(hp[j]);
            acc[2 * j + 0] = fmaf(w, f.x, acc[2 * j + 0]);
            acc[2 * j + 1] = fmaf(w, f.y, acc[2 * j + 1]);
        }
    }

    // reduce over corner groups
#pragma unroll
    for (int s = 4; s <= 8; s <<= 1)
#pragma unroll
        for (int j = 0; j < 8; j++)
            acc[j] += __shfl_xor_sync(0xffffffffu, acc[j], s);

    if (cr == 0) {
        uint4 hv;
        uint32_t* hw = (uint32_t*)&hv;
#pragma unroll
        for (int j = 0; j < 4; j++)
            hw[j] = packh2(acc[2 * j], acc[2 * j + 1]);
        const size_t o = (size_t)q * 256 + h * 32 + e * 8;
        *(uint4*)&accb[o] = hv;
    }
}

// ---------------------------------------------------------------------------
// Launch
// ---------------------------------------------------------------------------
extern "C" void kernel_launch(void* const* d_in, const int* in_sizes, int n_in,
                              void* d_out, int out_size)
{
    const float* query    = (const float*)d_in[0];
    const float* value_in = (const float*)d_in[1];
    const float* rp       = (const float*)d_in[2];
    const float* Wv       = (const float*)d_in[3];
    const float* bv       = (const float*)d_in[4];
    const float* Ws       = (const float*)d_in[5];
    const float* bs       = (const float*)d_in[6];
    const float* Wa       = (const float*)d_in[7];
    const float* ba       = (const float*)d_in[8];
    const float* Wo       = (const float*)d_in[9];
    const float* bo       = (const float*)d_in[10];
    float* out = (float*)d_out;

    __half *pvh, *pac, *pwv, *pwq, *pwo;
    float *pq, *pbq;
    cudaGetSymbolAddress((void**)&pvh, g_value_h);
    cudaGetSymbolAddress((void**)&pq,  g_qout);
    cudaGetSymbolAddress((void**)&pac, g_acc);
    cudaGetSymbolAddress((void**)&pbq, g_bq);
    cudaGetSymbolAddress((void**)&pwv, g_Wv);
    cudaGetSymbolAddress((void**)&pwq, g_Wq);
    cudaGetSymbolAddress((void**)&pwo, g_Wo);

    const int SMEM = 81920;   // 16K A + 64K B -> 2 CTAs/SM
    cudaFuncSetAttribute(proj_fused, cudaFuncAttributeMaxDynamicSharedMemorySize, SMEM);
    cudaFuncSetAttribute(gemm_out,   cudaFuncAttributeMaxDynamicSharedMemorySize, SMEM);

    const int M = LQ;
    const int GBY = (M + 127) / 128;            // 337
    const int ZCOLS = (ZPB + GBY - 1) / GBY;    // extra bx columns for zero-pad
    dim3 blk(256);

    // Weight prep (weights + bias only)
    prep_weights<<<(229760 + 255) / 256, 256>>>(Wv, Ws, Wa, Wo, bs, ba,
                                                pwv, pwq, pwo, pbq);

    // Fused value + offsets/logits projections + value border zeroing
    proj_fused<<<dim3(5 + ZCOLS, GBY), blk, SMEM>>>(
        value_in, query, pwv, pwq, bv, pbq, pvh, pq, M, GBY);

    // Deformable sampling: 4 queries/block (LQ = 43054 = 2 * 21527; pad to mult of 4)
    msda_sample<<<(LQ + 3) / 4, 512>>>(pvh, pq, rp, pac);

    // Output projection
    gemm_out<<<dim3(2, GBY), blk, SMEM>>>(pac, pwo, bo, out, M);
}

// round 16
// speedup vs baseline: 1.0257x; 1.0257x over previous
#include <cuda_runtime.h>
#include <cuda_bf16.h>
#include <cuda_fp16.h>
#include <cstdint>

// Problem constants
#define LQ      43054
#define NHEADS  8

// Padded value geometry: each level padded +2 on every side.
#define PADROWS 45822
#define ZPN     (PADROWS * 8)     // one zero-task per (pixel, head)

// Scratch (device globals; no runtime allocation allowed)
// Head-major padded value: [head][padded pixel][32 fp16] (64B per pixel-head)
__device__ __half g_value_h[NHEADS * PADROWS * 32];
__device__ __half g_qout[LQ * 384];             // fp16: [0,256)=offsets, [256,384)=logits
__device__ __half g_acc[LQ * 256];              // msda out (fp16)
__device__ __half g_Wv[256 * 256];
__device__ __half g_Wq[384 * 256];              // merged Ws|Wa
__device__ __half g_Wo[256 * 256];
__device__ float g_bq[384];                     // merged bias bs|ba

#define SW128(o) ((o) ^ (((o) >> 3) & 0x70))

__device__ __forceinline__ uint32_t smem_u32(const void* p) {
    uint32_t a;
    asm("{ .reg .u64 t; cvta.to.shared.u64 t, %1; cvt.u32.u64 %0, t; }" : "=r"(a) : "l"(p));
    return a;
}
__device__ __forceinline__ void ldsm4(uint32_t r[4], uint32_t addr) {
    asm volatile("ldmatrix.sync.aligned.m8n8.x4.shared.b16 {%0,%1,%2,%3}, [%4];"
        : "=r"(r[0]), "=r"(r[1]), "=r"(r[2]), "=r"(r[3]) : "r"(addr));
}
__device__ __forceinline__ void mma_f16(float d[4], const uint32_t a[4],
                                        uint32_t b0, uint32_t b1) {
    asm volatile("mma.sync.aligned.m16n8k16.row.col.f32.f16.f16.f32 "
        "{%0,%1,%2,%3}, {%4,%5,%6,%7}, {%8,%9}, {%0,%1,%2,%3};"
        : "+f"(d[0]), "+f"(d[1]), "+f"(d[2]), "+f"(d[3])
        : "r"(a[0]), "r"(a[1]), "r"(a[2]), "r"(a[3]), "r"(b0), "r"(b1));
}
__device__ __forceinline__ uint32_t packh2(float x, float y) {
    __half2 h = __floats2half2_rn(x, y);
    return *(uint32_t*)&h;
}
__device__ __forceinline__ void cpa16(uint32_t d, const void* s) {
    asm volatile("cp.async.cg.shared.global [%0], [%1], 16;" :: "r"(d), "l"(s));
}
#define CP_COMMIT() asm volatile("cp.async.commit_group;" ::: "memory")
template <int Ngrp>
__device__ __forceinline__ void cp_wait() {
    asm volatile("cp.async.wait_group %0;" :: "n"(Ngrp) : "memory");
}

// Map original value row -> padded row index (compile-time divisors).
__device__ __forceinline__ int pad_row(int r) {
    if (r < 32400) { int cy = r / 180, cx = r - cy * 180; return (cy + 2) * 184 + cx + 2; }
    if (r < 40500) { int rr = r - 32400; int cy = rr / 90, cx = rr - cy * 90; return 33856 + (cy + 2) * 94 + cx + 2; }
    if (r < 42525) { int rr = r - 40500; int cy = rr / 45, cx = rr - cy * 45; return 42692 + (cy + 2) * 49 + cx + 2; }
    { int rr = r - 42525; int cy = rr / 23, cx = rr - cy * 23; return 45093 + (cy + 2) * 27 + cx + 2; }
}

// ---------------------------------------------------------------------------
// Combined prep: zero padding borders (head-major) + fp16 weights + bias.
// ---------------------------------------------------------------------------
__global__ __launch_bounds__(256) void prep_all(
    const float* __restrict__ Wv, const float* __restrict__ Ws,
    const float* __restrict__ Wa, const float* __restrict__ Wo,
    const float* __restrict__ bs, const float* __restrict__ ba,
    __half* __restrict__ vp,
    __half* __restrict__ wv, __half* __restrict__ wq, __half* __restrict__ wo,
    float* __restrict__ bq)
{
    int idx = blockIdx.x * 256 + threadIdx.x;
    if (idx < ZPN) {
        int row = idx >> 3, h = idx & 7;
        bool pad;
        if (row < 33856)      { int py = row / 184, px = row - py * 184;
                                pad = (py < 2) | (py >= 182) | (px < 2) | (px >= 182); }
        else if (row < 42692) { int r2 = row - 33856; int py = r2 / 94, px = r2 - py * 94;
                                pad = (py < 2) | (py >= 92) | (px < 2) | (px >= 92); }
        else if (row < 45093) { int r2 = row - 42692; int py = r2 / 49, px = r2 - py * 49;
                                pad = (py < 2) | (py >= 47) | (px < 2) | (px >= 47); }
        else                  { int r2 = row - 45093; int py = r2 / 27, px = r2 - py * 27;
                                pad = (py < 2) | (py >= 25) | (px < 2) | (px >= 25); }
        if (pad) {
            uint4* d = (uint4*)((char*)vp + ((size_t)h * PADROWS + row) * 64);
            d[0] = make_uint4(0, 0, 0, 0);
            d[1] = make_uint4(0, 0, 0, 0);
            d[2] = make_uint4(0, 0, 0, 0);
            d[3] = make_uint4(0, 0, 0, 0);
        }
        return;
    }
    idx -= ZPN;
    const float* W;
    __half* dst;
    int N, base, nofs;
    if (idx < 65536)        { W = Wv; dst = wv; N = 256; base = 0;      nofs = 0; }
    else if (idx < 131072)  { W = Ws; dst = wq; N = 256; base = 65536;  nofs = 0; }
    else if (idx < 163840)  { W = Wa; dst = wq; N = 128; base = 131072; nofs = 256; }
    else if (idx < 229376)  { W = Wo; dst = wo; N = 256; base = 163840; nofs = 0; }
    else if (idx < 229376 + 256) { bq[idx - 229376] = bs[idx - 229376]; return; }
    else if (idx < 229376 + 384) { bq[idx - 229376] = ba[idx - 229632]; return; }
    else return;
    int j = idx - base;
    int k = j / N, n = j % N + nofs;
    dst[n * 256 + k] = __float2half_rn(W[j]);
}

// ---------------------------------------------------------------------------
// Fused projection kernel: one launch does BOTH
//   bx<2 : value path  -> head-major padded fp16 value
//   bx>=2: q path      -> fp16 [Lq,384] offsets|logits
// ---------------------------------------------------------------------------
__global__ __launch_bounds__(256, 2) void proj_fused(
    const float* __restrict__ Av, const float* __restrict__ Aq,
    const __half* __restrict__ Bv, const __half* __restrict__ Bq,
    const float* __restrict__ biasv, const float* __restrict__ biasq,
    __half* __restrict__ Cv, __half* __restrict__ Cq, int M)
{
    extern __shared__ char smem[];
    const uint32_t sb = smem_u32(smem);
    constexpr int BOFF = 16384;

    const bool vpath = blockIdx.x < 2;
    const int bn = (vpath ? blockIdx.x : blockIdx.x - 2) * 128;
    const float* __restrict__ A = vpath ? Av : Aq;
    const __half* __restrict__ B = vpath ? Bv : Bq;
    const float* __restrict__ bias = vpath ? biasv : biasq;

    const int tid = threadIdx.x;
    const int wid = tid >> 5, lane = tid & 31;
    const int wm = (wid & 3) * 32;
    const int wn = (wid >> 2) * 64;
    const int bm = blockIdx.y * 128;

    float acc[2][8][4];
#pragma unroll
    for (int i = 0; i < 2; i++)
#pragma unroll
        for (int j = 0; j < 8; j++)
#pragma unroll
            for (int k = 0; k < 4; k++) acc[i][j][k] = 0.f;

    const int a_row = lane & 15;
    const int a_k8  = (lane >> 4) << 3;
    const int b_row = (lane & 7) + ((lane & 16) >> 1);
    const int b_k8  = lane & 8;

    const int ld_row = tid >> 1;
    const int ld_kh  = (tid & 1) * 32;
    const int grow   = bm + ld_row;
    const bool okA   = grow < M;

    auto issueB = [&](int c) {
        const int k0 = c * 64;
        const int n = bn + ld_row;
        const __half* s = &B[(size_t)n * 256 + k0 + ld_kh];
        const uint32_t bas = sb + BOFF + c * 16384;
#pragma unroll
        for (int jj = 0; jj < 4; jj++) {
            uint32_t off = SW128((uint32_t)(ld_row * 128 + (ld_kh + jj * 8) * 2));
            cpa16(bas + off, s + jj * 8);
        }
    };

    float4 vA[8];
    auto stageA = [&](int c) {
        const int k0 = c * 64;
        const float4* src = (const float4*)&A[(size_t)(okA ? grow : 0) * 256 + k0 + ld_kh];
#pragma unroll
        for (int j = 0; j < 8; j++)
            vA[j] = okA ? src[j] : make_float4(0.f, 0.f, 0.f, 0.f);
    };
    auto commitA = [&]() {
#pragma unroll
        for (int jj = 0; jj < 4; jj++) {
            float4 v0 = vA[jj * 2 + 0];
            float4 v1 = vA[jj * 2 + 1];
            uint4 hi4;
            uint32_t* hp = (uint32_t*)&hi4;
            hp[0] = packh2(v0.x, v0.y);
            hp[1] = packh2(v0.z, v0.w);
            hp[2] = packh2(v1.x, v1.y);
            hp[3] = packh2(v1.z, v1.w);
            uint32_t off = SW128((uint32_t)(ld_row * 128 + (ld_kh + jj * 8) * 2));
            *(uint4*)(smem + off) = hi4;
        }
    };

    auto mma_chunk = [&](uint32_t bB) {
#pragma unroll
        for (int ks = 0; ks < 4; ks++) {
            uint32_t ah[2][4];
#pragma unroll
            for (int mt = 0; mt < 2; mt++) {
                uint32_t aoff = SW128((uint32_t)((wm + mt * 16 + a_row) * 128 +
                                                 (ks * 16 + a_k8) * 2));
                ldsm4(ah[mt], sb + aoff);
            }
#pragma unroll
            for (int ng = 0; ng < 4; ng++) {
                uint32_t boff = SW128((uint32_t)((wn + ng * 16 + b_row) * 128 +
                                                 (ks * 16 + b_k8) * 2));
                uint32_t b4[4];
                ldsm4(b4, bB + boff);
#pragma unroll
                for (int mt = 0; mt < 2; mt++) {
                    mma_f16(acc[mt][ng * 2 + 0], ah[mt], b4[0], b4[1]);
                    mma_f16(acc[mt][ng * 2 + 1], ah[mt], b4[2], b4[3]);
                }
            }
        }
    };

    issueB(0); CP_COMMIT();
    issueB(1); CP_COMMIT();
    issueB(2); CP_COMMIT();
    issueB(3); CP_COMMIT();
    stageA(0);
#pragma unroll
    for (int c = 0; c < 4; c++) {
        if (c > 0) __syncthreads();
        commitA();
        if (c < 3) stageA(c + 1);
        if (c == 0) cp_wait<3>();
        else if (c == 1) cp_wait<2>();
        else if (c == 2) cp_wait<1>();
        else cp_wait<0>();
        __syncthreads();
        mma_chunk(sb + BOFF + c * 16384);
    }

    // epilogue
    const int g = lane >> 2;
    const int cb = wn + (lane & 3) * 2;
    if (vpath) {
        int prow[2][2];
#pragma unroll
        for (int mt = 0; mt < 2; mt++) {
            int r0 = bm + wm + mt * 16 + g;
            prow[mt][0] = (r0 < M) ? pad_row(r0) : 0;
            prow[mt][1] = (r0 + 8 < M) ? pad_row(r0 + 8) : 0;
        }
#pragma unroll
        for (int nt = 0; nt < 8; nt++) {
            const int col = bn + cb + nt * 8;
            const int hh = col >> 5, ch = col & 31;
            const float b0 = bias[col], b1 = bias[col + 1];
#pragma unroll
            for (int mt = 0; mt < 2; mt++) {
                int r0 = bm + wm + mt * 16 + g;
                if (r0 < M)
                    *(__half2*)&Cv[((size_t)hh * PADROWS + prow[mt][0]) * 32 + ch] =
                        __floats2half2_rn(acc[mt][nt][0] + b0, acc[mt][nt][1] + b1);
                if (r0 + 8 < M)
                    *(__half2*)&Cv[((size_t)hh * PADROWS + prow[mt][1]) * 32 + ch] =
                        __floats2half2_rn(acc[mt][nt][2] + b0, acc[mt][nt][3] + b1);
            }
        }
    } else {
#pragma unroll
        for (int nt = 0; nt < 8; nt++) {
            const int col = bn + cb + nt * 8;
            const float b0 = bias[col], b1 = bias[col + 1];
#pragma unroll
            for (int mt = 0; mt < 2; mt++) {
                int r0 = bm + wm + mt * 16 + g;
                if (r0 < M)
                    *(__half2*)&Cq[(size_t)r0 * 384 + col] =
                        __floats2half2_rn(acc[mt][nt][0] + b0, acc[mt][nt][1] + b1);
                if (r0 + 8 < M)
                    *(__half2*)&Cq[(size_t)(r0 + 8) * 384 + col] =
                        __floats2half2_rn(acc[mt][nt][2] + b0, acc[mt][nt][3] + b1);
            }
        }
    }
}

// ---------------------------------------------------------------------------
// Output GEMM: out (fp32, N=256) = acc (fp16) @ Wo + bo
// ---------------------------------------------------------------------------
__global__ __launch_bounds__(256, 2) void gemm_out(
    const __half* __restrict__ AhG,
    const __half* __restrict__ B,
    const float* __restrict__ bias,
    float* __restrict__ C, int M)
{
    extern __shared__ char smem[];
    const uint32_t sb = smem_u32(smem);
    constexpr int BOFF = 16384;

    const int tid = threadIdx.x;
    const int wid = tid >> 5, lane = tid & 31;
    const int wm = (wid & 3) * 32;
    const int wn = (wid >> 2) * 64;
    const int bm = blockIdx.y * 128;
    const int bn = blockIdx.x * 128;

    float acc[2][8][4];
#pragma unroll
    for (int i = 0; i < 2; i++)
#pragma unroll
        for (int j = 0; j < 8; j++)
#pragma unroll
            for (int k = 0; k < 4; k++) acc[i][j][k] = 0.f;

    const int a_row = lane & 15;
    const int a_k8  = (lane >> 4) << 3;
    const int b_row = (lane & 7) + ((lane & 16) >> 1);
    const int b_k8  = lane & 8;

    const int ld_row = tid >> 1;
    const int ld_kh  = (tid & 1) * 32;
    const int grow   = bm + ld_row;
    const bool okA   = grow < M;

    auto issueB = [&](int c) {
        const int k0 = c * 64;
        const int n = bn + ld_row;
        const __half* s = &B[(size_t)n * 256 + k0 + ld_kh];
        const uint32_t bas = sb + BOFF + c * 16384;
#pragma unroll
        for (int jj = 0; jj < 4; jj++) {
            uint32_t off = SW128((uint32_t)(ld_row * 128 + (ld_kh + jj * 8) * 2));
            cpa16(bas + off, s + jj * 8);
        }
    };

    uint4 sA[4];
    auto stageA = [&](int c) {
        const int k0 = c * 64;
        const uint4* sh = (const uint4*)&AhG[(size_t)(okA ? grow : 0) * 256 + k0 + ld_kh];
#pragma unroll
        for (int j = 0; j < 4; j++)
            sA[j] = okA ? sh[j] : make_uint4(0, 0, 0, 0);
    };
    auto commitA = [&]() {
#pragma unroll
        for (int jj = 0; jj < 4; jj++) {
            uint32_t off = SW128((uint32_t)(ld_row * 128 + (ld_kh + jj * 8) * 2));
            *(uint4*)(smem + off) = sA[jj];
        }
    };

    auto mma_chunk = [&](uint32_t bB) {
#pragma unroll
        for (int ks = 0; ks < 4; ks++) {
            uint32_t ah[2][4];
#pragma unroll
            for (int mt = 0; mt < 2; mt++) {
                uint32_t aoff = SW128((uint32_t)((wm + mt * 16 + a_row) * 128 +
                                                 (ks * 16 + a_k8) * 2));
                ldsm4(ah[mt], sb + aoff);
            }
#pragma unroll
            for (int ng = 0; ng < 4; ng++) {
                uint32_t boff = SW128((uint32_t)((wn + ng * 16 + b_row) * 128 +
                                                 (ks * 16 + b_k8) * 2));
                uint32_t b4[4];
                ldsm4(b4, bB + boff);
#pragma unroll
                for (int mt = 0; mt < 2; mt++) {
                    mma_f16(acc[mt][ng * 2 + 0], ah[mt], b4[0], b4[1]);
                    mma_f16(acc[mt][ng * 2 + 1], ah[mt], b4[2], b4[3]);
                }
            }
        }
    };

    issueB(0); CP_COMMIT();
    issueB(1); CP_COMMIT();
    issueB(2); CP_COMMIT();
    issueB(3); CP_COMMIT();
    stageA(0);
#pragma unroll
    for (int c = 0; c < 4; c++) {
        if (c > 0) __syncthreads();
        commitA();
        if (c < 3) stageA(c + 1);
        if (c == 0) cp_wait<3>();
        else if (c == 1) cp_wait<2>();
        else if (c == 2) cp_wait<1>();
        else cp_wait<0>();
        __syncthreads();
        mma_chunk(sb + BOFF + c * 16384);
    }

    const int g = lane >> 2;
    const int cbase = bn + wn + (lane & 3) * 2;
#pragma unroll
    for (int nt = 0; nt < 8; nt++) {
        const int col = cbase + nt * 8;
        const float b0 = bias[col], b1 = bias[col + 1];
#pragma unroll
        for (int mt = 0; mt < 2; mt++) {
            int r0 = bm + wm + mt * 16 + g;
            if (r0 < M)
                *(float2*)&C[(size_t)r0 * 256 + col] =
                    make_float2(acc[mt][nt][0] + b0, acc[mt][nt][1] + b1);
            if (r0 + 8 < M)
                *(float2*)&C[(size_t)(r0 + 8) * 256 + col] =
                    make_float2(acc[mt][nt][2] + b0, acc[mt][nt][3] + b1);
        }
    }
}

// ---------------------------------------------------------------------------
// Sampling kernel: head-major value layout. 2 queries/block, 2 heads/warp.
// fp16 qout input.
// ---------------------------------------------------------------------------
__global__ __launch_bounds__(256) void msda_sample(
    const __half* __restrict__ value,    // [8][PADROWS][32] fp16
    const __half* __restrict__ qout,     // [Lq,384] fp16 offsets|logits
    const float* __restrict__ rp,        // [Lq,4,2]
    __half* __restrict__ accb)
{
    constexpr int WW[4] = {180, 90, 45, 23};
    constexpr int PB[4] = {0, 33856, 42692, 45093};

    __shared__ uint2 swo[2][NHEADS][16][4];   // [q-half][head][point][corner]

    const int tid = threadIdx.x;
    const int qi = tid >> 7;
    const int q = blockIdx.x * 2 + qi;
    const int t7 = tid & 127;
    const int wid = t7 >> 5;
    const int lane = tid & 31;
    const int h2 = lane >> 4;
    const int h  = wid * 2 + h2;
    const int pt = lane & 15;
    const int cr = (lane >> 2) & 3;
    const int e  = lane & 3;

    // softmax over this head's 16 logits
    const float lg = __half2float(qout[q * 384 + 256 + h * 16 + pt]);
    float m = lg;
#pragma unroll
    for (int s = 8; s > 0; s >>= 1)
        m = fmaxf(m, __shfl_xor_sync(0xffffffffu, m, s));
    const float eo = __expf(lg - m);
    float ssum = eo;
#pragma unroll
    for (int s = 8; s > 0; s >>= 1)
        ssum += __shfl_xor_sync(0xffffffffu, ssum, s);
    const float aw = eo / ssum;

    // geometry: all 32 lanes (2 heads x 16 points)
    {
        const int l = pt >> 2;
        const int p = pt & 3;
        const int W = WW[l];
        const float2 rxy = *(const float2*)&rp[(q * 4 + l) * 2];
        const int oj = q * 384 + (((h * 4 + l) * 4) + p) * 2;
        const float2 oxy = __half22float2(*(const __half2*)&qout[oj]);
        const float x = fmaf(rxy.x, (float)W, oxy.x) - 0.5f;
        const float y = fmaf(rxy.y, (float)W, oxy.y) - 0.5f;
        const float xf = floorf(x), yf = floorf(y);
        const float dx = x - xf, dy = y - yf;
        const int xc = min(max((int)xf, -2), W);
        const int yc = min(max((int)yf, -2), W);
        const int B0 = (PB[l] + (yc + 2) * (W + 4) + (xc + 2)) * 64;   // 64B/pixel
        const float wx1 = aw * dx;
        const float wx0 = aw - wx1;
#pragma unroll
        for (int c = 0; c < 4; c++) {
            const int cxx = c & 1, cyy = c >> 1;
            const int off = B0 + (cyy * (W + 4) + cxx) * 64;
            const float w = (cxx ? wx1 : wx0) * (cyy ? dy : (1.f - dy));
            swo[qi][h][pt][c] = make_uint2(__float_as_uint(w), (uint32_t)off);
        }
    }
    __syncwarp();

    // gather: one LDG.128 per point per lane (16B of a corner pixel)
    const char* __restrict__ vb = (const char*)value + (size_t)h * PADROWS * 64 + e * 16;
    const uint2* __restrict__ sp = &swo[qi][h][0][cr];
    float acc[8];
#pragma unroll
    for (int j = 0; j < 8; j++) acc[j] = 0.f;

#pragma unroll
    for (int i = 0; i < 16; i++) {
        const uint2 wo = sp[i * 4];
        const float w = __uint_as_float(wo.x);
        const uint4 raw = *(const uint4*)(vb + wo.y);
        const __half2* hp = (const __half2*)&raw;
#pragma unroll
        for (int j = 0; j < 4; j++) {
            const float2 f = __half22float2(hp[j]);
            acc[2 * j + 0] = fmaf(w, f.x, acc[2 * j + 0]);
            acc[2 * j + 1] = fmaf(w, f.y, acc[2 * j + 1]);
        }
    }

    // reduce over corner groups
#pragma unroll
    for (int s = 4; s <= 8; s <<= 1)
#pragma unroll
        for (int j = 0; j < 8; j++)
            acc[j] += __shfl_xor_sync(0xffffffffu, acc[j], s);

    if (cr == 0) {
        uint4 hv;
        uint32_t* hw = (uint32_t*)&hv;
#pragma unroll
        for (int j = 0; j < 4; j++)
            hw[j] = packh2(acc[2 * j], acc[2 * j + 1]);
        const size_t o = (size_t)q * 256 + h * 32 + e * 8;
        *(uint4*)&accb[o] = hv;
    }
}

// ---------------------------------------------------------------------------
// Launch
// ---------------------------------------------------------------------------
extern "C" void kernel_launch(void* const* d_in, const int* in_sizes, int n_in,
                              void* d_out, int out_size)
{
    const float* query    = (const float*)d_in[0];
    const float* value_in = (const float*)d_in[1];
    const float* rp       = (const float*)d_in[2];
    const float* Wv       = (const float*)d_in[3];
    const float* bv       = (const float*)d_in[4];
    const float* Ws       = (const float*)d_in[5];
    const float* bs       = (const float*)d_in[6];
    const float* Wa       = (const float*)d_in[7];
    const float* ba       = (const float*)d_in[8];
    const float* Wo       = (const float*)d_in[9];
    const float* bo       = (const float*)d_in[10];
    float* out = (float*)d_out;

    __half *pvh, *pq, *pac, *pwv, *pwq, *pwo;
    float *pbq;
    cudaGetSymbolAddress((void**)&pvh, g_value_h);
    cudaGetSymbolAddress((void**)&pq,  g_qout);
    cudaGetSymbolAddress((void**)&pac, g_acc);
    cudaGetSymbolAddress((void**)&pbq, g_bq);
    cudaGetSymbolAddress((void**)&pwv, g_Wv);
    cudaGetSymbolAddress((void**)&pwq, g_Wq);
    cudaGetSymbolAddress((void**)&pwo, g_Wo);

    const int SMEM = 81920;   // 16K A + 64K B -> 2 CTAs/SM
    cudaFuncSetAttribute(proj_fused, cudaFuncAttributeMaxDynamicSharedMemorySize, SMEM);
    cudaFuncSetAttribute(gemm_out,   cudaFuncAttributeMaxDynamicSharedMemorySize, SMEM);

    const int M = LQ;
    const int GBY = (M + 127) / 128;  // 337
    dim3 blk(256);

    // Combined prep (zero pads + weights + bias), single launch
    prep_all<<<(ZPN + 229760 + 255) / 256, 256>>>(Wv, Ws, Wa, Wo, bs, ba,
                                                  pvh, pwv, pwq, pwo, pbq);

    // Fused value + offsets/logits projections (one launch)
    proj_fused<<<dim3(5, GBY), blk, SMEM>>>(
        value_in, query, pwv, pwq, bv, pbq, pvh, pq, M);

    // Deformable sampling: 2 queries/block, 2 heads/warp, head-major value
    msda_sample<<<LQ / 2, 256>>>(pvh, pq, rp, pac);

    // Output projection
    gemm_out<<<dim3(2, GBY), blk, SMEM>>>(pac, pwo, bo, out, M);
}